// round 7
// baseline (speedup 1.0000x reference)
#include <cuda_runtime.h>

#define NB     131072      // 32768 centers * 4 species
#define MAXE   1048576

namespace {

constexpr float PI_F   = 3.14159265358979323846f;
constexpr float NORM_F = 0.17677669529663687f;   // 1/sqrt(32)

__device__ int    g_cnt[NB];
__device__ int    g_cur[NB];
__device__ int    g_blk[128];
__device__ float4 g_edges[MAXE];

__device__ __forceinline__ void red_add_v4(float* p, float a, float b, float c, float d) {
    unsigned long long gp = __cvta_generic_to_global(p);
    asm volatile("red.global.add.v4.f32 [%0], {%1, %2, %3, %4};"
                 :: "l"(gp), "f"(a), "f"(b), "f"(c), "f"(d)
                 : "memory");
}

// ------------------------------------------------------------ histogram
__global__ void k_hist(const int* __restrict__ cidx,
                       const int* __restrict__ sidx, int n) {
    int e = blockIdx.x * blockDim.x + threadIdx.x;
    if (e < n) atomicAdd(&g_cnt[cidx[e] * 4 + sidx[e]], 1);
}

// ------------------------------------------------------------ scan step A
__global__ void k_scanA() {            // 128 blocks x 256 threads
    __shared__ int sm[256];
    int t = threadIdx.x, blk = blockIdx.x;
    int base = blk * 1024 + t * 4;
    int4 c = *reinterpret_cast<const int4*>(&g_cnt[base]);
    int s = c.x + c.y + c.z + c.w;
    sm[t] = s;
    __syncthreads();
    #pragma unroll
    for (int off = 1; off < 256; off <<= 1) {
        int v = (t >= off) ? sm[t - off] : 0;
        __syncthreads();
        sm[t] += v;
        __syncthreads();
    }
    int ex = sm[t] - s;                // exclusive within CTA
    int4 o;
    o.x = ex; o.y = ex + c.x; o.z = o.y + c.y; o.w = o.z + c.z;
    *reinterpret_cast<int4*>(&g_cur[base]) = o;
    if (t == 255) g_blk[blk] = sm[255];
}

// ------------------------------------------------------------ scan step B+C fused
// 128 blocks x 256 threads: each block re-reduces g_blk[0..blk) itself
__global__ void k_scanC() {
    __shared__ int s_wsum[8];
    __shared__ int s_off;
    int t = threadIdx.x, blk = blockIdx.x;

    int contrib = (t < 128 && t < blk) ? g_blk[t] : 0;
    #pragma unroll
    for (int o = 16; o; o >>= 1)
        contrib += __shfl_down_sync(0xffffffffu, contrib, o);
    if ((t & 31) == 0) s_wsum[t >> 5] = contrib;
    __syncthreads();
    if (t == 0) {
        int a = 0;
        #pragma unroll
        for (int i = 0; i < 8; i++) a += s_wsum[i];
        s_off = a;
    }
    __syncthreads();
    int off = s_off;

    int i = blk * 256 + t;             // 32768 threads, 4 buckets each
    int4 v = *reinterpret_cast<int4*>(&g_cur[i * 4]);
    v.x += off; v.y += off; v.z += off; v.w += off;
    *reinterpret_cast<int4*>(&g_cur[i * 4]) = v;
}

// ------------------------------------------------------------ scatter (sort)
__global__ void k_scatter(const float* __restrict__ vec,
                          const int* __restrict__ cidx,
                          const int* __restrict__ sidx, int n) {
    int e = blockIdx.x * blockDim.x + threadIdx.x;
    if (e >= n) return;
    int b = cidx[e] * 4 + sidx[e];
    int p = atomicAdd(&g_cur[b], 1);
    g_edges[p] = make_float4(vec[3 * e], vec[3 * e + 1], vec[3 * e + 2],
                             __int_as_float(b));
}

// ------------------------------------------------------------ accumulate
// 256 threads = 8 warps; each warp owns 32 consecutive sorted edges.
// Complete-bucket segments use plain st.v4 (no atomic); partial ones red.v4.
__global__ __launch_bounds__(256)
void k_accum(const float* __restrict__ W, float* __restrict__ out, int n) {
    __shared__ float sW[384];
    __shared__ float s_sh[8][16 * 33];     // [warp][k*33 + edge]
    __shared__ float s_rad[8][8 * 132];    // [warp][q*132 + edge*4 + c]
    __shared__ int   s_bkt[8][32];

    int t = threadIdx.x, w = t >> 5, lane = t & 31;
    for (int i = t; i < 384; i += 256) sW[i] = W[i];
    __syncthreads();

    int wbase = blockIdx.x * 256 + w * 32;
    int e = wbase + lane;
    int b = -1;
    float4 v = make_float4(0.f, 0.f, 0.f, 0.f);
    if (e < n) { v = g_edges[e]; b = __float_as_int(v.w); }
    s_bkt[w][lane] = b;

    float rad[32];
    float sh[16];
    #pragma unroll
    for (int i = 0; i < 32; i++) rad[i] = 0.f;
    #pragma unroll
    for (int i = 0; i < 16; i++) sh[i] = 0.f;

    if (b >= 0) {
        float vx = v.x, vy = v.y, vz = v.z;
        float r2   = fmaf(vx, vx, fmaf(vy, vy, vz * vz)) + 1e-12f;
        float rinv = rsqrtf(r2);
        float r    = r2 * rinv;
        float x = vx * rinv, y = vy * rinv, z = vz * rinv;

        float a = (PI_F / 5.0f) * r;
        float s0, c0;
        __sincosf(a, &s0, &c0);
        float tt    = NORM_F * rinv;
        float two_c = 2.0f * c0;
        float phi[12];
        {
            float sm1 = 0.f, sc = s0;
            phi[0] = sc * tt;
            #pragma unroll
            for (int nn = 1; nn < 12; nn++) {
                float s1 = fmaf(two_c, sc, -sm1);
                sm1 = sc; sc = s1;
                phi[nn] = sc * tt;
            }
        }

        // rad[l*8 + n] = sum_b phi[b] * W[l][b][n]  (float4 smem loads)
        const float4* w4 = reinterpret_cast<const float4*>(sW);
        #pragma unroll
        for (int bb = 0; bb < 12; bb++) {
            float p = phi[bb];
            #pragma unroll
            for (int l = 0; l < 4; l++) {
                float4 w0 = w4[l * 24 + bb * 2 + 0];
                float4 w1 = w4[l * 24 + bb * 2 + 1];
                rad[l * 8 + 0] = fmaf(p, w0.x, rad[l * 8 + 0]);
                rad[l * 8 + 1] = fmaf(p, w0.y, rad[l * 8 + 1]);
                rad[l * 8 + 2] = fmaf(p, w0.z, rad[l * 8 + 2]);
                rad[l * 8 + 3] = fmaf(p, w0.w, rad[l * 8 + 3]);
                rad[l * 8 + 4] = fmaf(p, w1.x, rad[l * 8 + 4]);
                rad[l * 8 + 5] = fmaf(p, w1.y, rad[l * 8 + 5]);
                rad[l * 8 + 6] = fmaf(p, w1.z, rad[l * 8 + 6]);
                rad[l * 8 + 7] = fmaf(p, w1.w, rad[l * 8 + 7]);
            }
        }

        float x2 = x * x, y2 = y * y, z2 = z * z;
        sh[0]  = 0.28209479177387814f;
        sh[1]  = 0.4886025119029199f * y;
        sh[2]  = 0.4886025119029199f * z;
        sh[3]  = 0.4886025119029199f * x;
        sh[4]  = 1.0925484305920792f * x * y;
        sh[5]  = 1.0925484305920792f * y * z;
        sh[6]  = 0.31539156525252005f * fmaf(3.0f, z2, -1.0f);
        sh[7]  = 1.0925484305920792f * x * z;
        sh[8]  = 0.5462742152960396f * (x2 - y2);
        sh[9]  = 0.5900435899266435f * y * fmaf(3.0f, x2, -y2);
        sh[10] = 2.890611442640554f  * x * y * z;
        sh[11] = 0.4570457994644658f * y * fmaf(5.0f, z2, -1.0f);
        sh[12] = 0.3731763325901154f * z * fmaf(5.0f, z2, -3.0f);
        sh[13] = 0.4570457994644658f * x * fmaf(5.0f, z2, -1.0f);
        sh[14] = 1.445305721320277f  * z * (x2 - y2);
        sh[15] = 0.5900435899266435f * x * (x2 - y2);
    }

    // stage to smem (bank-conflict-free layouts)
    #pragma unroll
    for (int k = 0; k < 16; k++) s_sh[w][k * 33 + lane] = sh[k];
    #pragma unroll
    for (int q = 0; q < 8; q++)
        *reinterpret_cast<float4*>(&s_rad[w][q * 132 + lane * 4]) =
            make_float4(rad[q * 4], rad[q * 4 + 1], rad[q * 4 + 2], rad[q * 4 + 3]);
    __syncwarp();

    // segment detection over sorted bucket ids
    int b_up = __shfl_up_sync(0xffffffffu, b, 1);
    bool head = (lane == 0) || (b != b_up);
    unsigned hm = __ballot_sync(0xffffffffu, head);

    int myk  = lane >> 1;
    int half = lane & 1;
    int l    = (myk >= 9) ? 3 : ((myk >= 4) ? 2 : ((myk >= 1) ? 1 : 0));
    int q    = l * 2 + half;
    const float* shrow  = &s_sh[w][myk * 33];
    const float* radrow = &s_rad[w][q * 132];

    unsigned m = hm;
    while (m) {
        int s = __ffs(m) - 1;
        m &= m - 1;
        int e2 = m ? (__ffs(m) - 1) : 32;
        int bs = s_bkt[w][s];
        if (bs >= 0) {
            float ax = 0.f, ay = 0.f, az = 0.f, aw = 0.f;
            for (int i = s; i < e2; i++) {
                float sk = shrow[i];
                float4 r = *reinterpret_cast<const float4*>(&radrow[i * 4]);
                ax = fmaf(sk, r.x, ax);
                ay = fmaf(sk, r.y, ay);
                az = fmaf(sk, r.z, az);
                aw = fmaf(sk, r.w, aw);
            }
            float* p = out + ((bs >> 2) * 512 + myk * 32 + (bs & 3) * 8 + half * 4);
            int end   = g_cur[bs];            // bucket end (post-scatter)
            int cnt   = g_cnt[bs];
            bool complete = (wbase + s == end - cnt) && (wbase + e2 == end);
            if (complete) {
                *reinterpret_cast<float4*>(p) = make_float4(ax, ay, az, aw);
            } else {
                red_add_v4(p, ax, ay, az, aw);
            }
        }
    }
}

} // namespace

extern "C" void kernel_launch(void* const* d_in, const int* in_sizes, int n_in,
                              void* d_out, int out_size)
{
    const float* vectors = (const float*)d_in[0];
    const float* W       = (const float*)d_in[1];
    const int*   cidx    = (const int*)d_in[2];
    const int*   sidx    = (const int*)d_in[3];
    float*       out     = (float*)d_out;

    int n_edges = in_sizes[2];

    static cudaStream_t s2 = nullptr;
    static cudaEvent_t evFork = nullptr, evJoin = nullptr;
    static void* cnt_ptr = nullptr;
    if (!s2) {
        cudaStreamCreate(&s2);
        cudaEventCreateWithFlags(&evFork, cudaEventDisableTiming);
        cudaEventCreateWithFlags(&evJoin, cudaEventDisableTiming);
        cudaGetSymbolAddress(&cnt_ptr, g_cnt);
    }

    // fork: big output memset runs concurrently with the sort pipeline
    cudaEventRecord(evFork, 0);
    cudaStreamWaitEvent(s2, evFork, 0);
    cudaMemsetAsync(d_out, 0, (size_t)out_size * sizeof(float), s2);

    // main pipeline
    cudaMemsetAsync(cnt_ptr, 0, NB * sizeof(int), 0);
    k_hist<<<(n_edges + 255) / 256, 256>>>(cidx, sidx, n_edges);
    k_scanA<<<128, 256>>>();
    k_scanC<<<128, 256>>>();
    k_scatter<<<(n_edges + 255) / 256, 256>>>(vectors, cidx, sidx, n_edges);

    // join: accum needs the zeroed output
    cudaEventRecord(evJoin, s2);
    cudaStreamWaitEvent(0, evJoin, 0);
    k_accum<<<(n_edges + 255) / 256, 256>>>(W, out, n_edges);
}

// round 8
// speedup vs baseline: 1.0446x; 1.0446x over previous
#include <cuda_runtime.h>

#define NB     131072      // 32768 centers * 4 species
#define MAXE   1048576

namespace {

constexpr float PI_F   = 3.14159265358979323846f;
constexpr float NORM_F = 0.17677669529663687f;   // 1/sqrt(32)

__device__ int    g_cnt[NB];
__device__ int    g_cur[NB];
__device__ int    g_blk[128];
__device__ float4 g_edges[MAXE];

__device__ __forceinline__ void red_add_v4(float* p, float a, float b, float c, float d) {
    unsigned long long gp = __cvta_generic_to_global(p);
    asm volatile("red.global.add.v4.f32 [%0], {%1, %2, %3, %4};"
                 :: "l"(gp), "f"(a), "f"(b), "f"(c), "f"(d)
                 : "memory");
}

// ------------------------------------------------------------ histogram (2 edges/thread)
__global__ void k_hist(const int* __restrict__ cidx,
                       const int* __restrict__ sidx, int n) {
    int i = blockIdx.x * blockDim.x + threadIdx.x;
    int e = i * 2;
    if (e + 1 < n) {
        int2 c = *reinterpret_cast<const int2*>(&cidx[e]);
        int2 s = *reinterpret_cast<const int2*>(&sidx[e]);
        atomicAdd(&g_cnt[c.x * 4 + s.x], 1);
        atomicAdd(&g_cnt[c.y * 4 + s.y], 1);
    } else if (e < n) {
        atomicAdd(&g_cnt[cidx[e] * 4 + sidx[e]], 1);
    }
}

// ------------------------------------------------------------ scan step A
__global__ void k_scanA() {            // 128 blocks x 256 threads
    __shared__ int sm[256];
    int t = threadIdx.x, blk = blockIdx.x;
    int base = blk * 1024 + t * 4;
    int4 c = *reinterpret_cast<const int4*>(&g_cnt[base]);
    int s = c.x + c.y + c.z + c.w;
    sm[t] = s;
    __syncthreads();
    #pragma unroll
    for (int off = 1; off < 256; off <<= 1) {
        int v = (t >= off) ? sm[t - off] : 0;
        __syncthreads();
        sm[t] += v;
        __syncthreads();
    }
    int ex = sm[t] - s;                // exclusive within CTA
    int4 o;
    o.x = ex; o.y = ex + c.x; o.z = o.y + c.y; o.w = o.z + c.z;
    *reinterpret_cast<int4*>(&g_cur[base]) = o;
    if (t == 255) g_blk[blk] = sm[255];
}

// ------------------------------------------------------------ scan step B+C fused
__global__ void k_scanC() {            // 128 blocks x 256 threads
    __shared__ int s_wsum[8];
    __shared__ int s_off;
    int t = threadIdx.x, blk = blockIdx.x;

    int contrib = (t < 128 && t < blk) ? g_blk[t] : 0;
    #pragma unroll
    for (int o = 16; o; o >>= 1)
        contrib += __shfl_down_sync(0xffffffffu, contrib, o);
    if ((t & 31) == 0) s_wsum[t >> 5] = contrib;
    __syncthreads();
    if (t == 0) {
        int a = 0;
        #pragma unroll
        for (int i = 0; i < 8; i++) a += s_wsum[i];
        s_off = a;
    }
    __syncthreads();
    int off = s_off;

    int i = blk * 256 + t;
    int4 v = *reinterpret_cast<int4*>(&g_cur[i * 4]);
    v.x += off; v.y += off; v.z += off; v.w += off;
    *reinterpret_cast<int4*>(&g_cur[i * 4]) = v;
}

// ------------------------------------------------------------ scatter (2 edges/thread)
__global__ void k_scatter(const float* __restrict__ vec,
                          const int* __restrict__ cidx,
                          const int* __restrict__ sidx, int n) {
    int i = blockIdx.x * blockDim.x + threadIdx.x;
    int e = i * 2;
    if (e + 1 < n) {
        int2 c = *reinterpret_cast<const int2*>(&cidx[e]);
        int2 s = *reinterpret_cast<const int2*>(&sidx[e]);
        float2 v0 = *reinterpret_cast<const float2*>(&vec[3 * e]);
        float2 v1 = *reinterpret_cast<const float2*>(&vec[3 * e + 2]);
        float2 v2 = *reinterpret_cast<const float2*>(&vec[3 * e + 4]);
        int b0 = c.x * 4 + s.x;
        int b1 = c.y * 4 + s.y;
        int p0 = atomicAdd(&g_cur[b0], 1);
        int p1 = atomicAdd(&g_cur[b1], 1);
        g_edges[p0] = make_float4(v0.x, v0.y, v1.x, __int_as_float(b0));
        g_edges[p1] = make_float4(v1.y, v2.x, v2.y, __int_as_float(b1));
    } else if (e < n) {
        int b = cidx[e] * 4 + sidx[e];
        int p = atomicAdd(&g_cur[b], 1);
        g_edges[p] = make_float4(vec[3 * e], vec[3 * e + 1], vec[3 * e + 2],
                                 __int_as_float(b));
    }
}

// ------------------------------------------------------------ accumulate
// 256 threads = 8 warps; each warp owns 32 consecutive sorted edges.
// Low-register variant: rad streamed to smem per-l (8 live accumulators),
// sh written straight to smem. Target 64 regs -> 4 CTAs/SM (32 warps).
__global__ __launch_bounds__(256, 4)
void k_accum(const float* __restrict__ W, float* __restrict__ out, int n) {
    __shared__ float sW[384];
    __shared__ float s_sh[8][16 * 33];     // [warp][k*33 + edge]
    __shared__ float s_rad[8][8 * 132];    // [warp][q*132 + edge*4 + c]
    __shared__ int   s_bkt[8][32];

    int t = threadIdx.x, w = t >> 5, lane = t & 31;
    for (int i = t; i < 384; i += 256) sW[i] = W[i];
    __syncthreads();

    int wbase = blockIdx.x * 256 + w * 32;
    int e = wbase + lane;
    int b = -1;
    float4 v = make_float4(0.f, 0.f, 0.f, 0.f);
    if (e < n) { v = g_edges[e]; b = __float_as_int(v.w); }
    s_bkt[w][lane] = b;

    {
        float vx = v.x, vy = v.y, vz = v.z;
        float r2   = fmaf(vx, vx, fmaf(vy, vy, vz * vz)) + 1e-12f;
        float rinv = rsqrtf(r2);
        float r    = r2 * rinv;
        float x = vx * rinv, y = vy * rinv, z = vz * rinv;
        if (b < 0) { x = 0.f; y = 0.f; z = 0.f; }

        // phi[b] = sin(pi/5 * r * (b+1)) / r * NORM  via Chebyshev recurrence
        float a = (PI_F / 5.0f) * r;
        float s0, c0;
        __sincosf(a, &s0, &c0);
        float tt    = (b >= 0) ? (NORM_F * rinv) : 0.f;
        float two_c = 2.0f * c0;
        float phi[12];
        {
            float sm1 = 0.f, sc = s0;
            phi[0] = sc * tt;
            #pragma unroll
            for (int nn = 1; nn < 12; nn++) {
                float s1 = fmaf(two_c, sc, -sm1);
                sm1 = sc; sc = s1;
                phi[nn] = sc * tt;
            }
        }

        // rad per l: 8 live accumulators, streamed to smem
        const float4* w4 = reinterpret_cast<const float4*>(sW);
        #pragma unroll
        for (int l = 0; l < 4; l++) {
            float r8[8];
            #pragma unroll
            for (int i = 0; i < 8; i++) r8[i] = 0.f;
            #pragma unroll
            for (int bb = 0; bb < 12; bb++) {
                float p = phi[bb];
                float4 w0 = w4[l * 24 + bb * 2 + 0];
                float4 w1 = w4[l * 24 + bb * 2 + 1];
                r8[0] = fmaf(p, w0.x, r8[0]);
                r8[1] = fmaf(p, w0.y, r8[1]);
                r8[2] = fmaf(p, w0.z, r8[2]);
                r8[3] = fmaf(p, w0.w, r8[3]);
                r8[4] = fmaf(p, w1.x, r8[4]);
                r8[5] = fmaf(p, w1.y, r8[5]);
                r8[6] = fmaf(p, w1.z, r8[6]);
                r8[7] = fmaf(p, w1.w, r8[7]);
            }
            *reinterpret_cast<float4*>(&s_rad[w][(l * 2 + 0) * 132 + lane * 4]) =
                make_float4(r8[0], r8[1], r8[2], r8[3]);
            *reinterpret_cast<float4*>(&s_rad[w][(l * 2 + 1) * 132 + lane * 4]) =
                make_float4(r8[4], r8[5], r8[6], r8[7]);
        }

        // sh straight to smem
        float x2 = x * x, y2 = y * y, z2 = z * z;
        float* sr = &s_sh[w][lane];
        sr[0  * 33] = 0.28209479177387814f;
        sr[1  * 33] = 0.4886025119029199f * y;
        sr[2  * 33] = 0.4886025119029199f * z;
        sr[3  * 33] = 0.4886025119029199f * x;
        sr[4  * 33] = 1.0925484305920792f * x * y;
        sr[5  * 33] = 1.0925484305920792f * y * z;
        sr[6  * 33] = 0.31539156525252005f * fmaf(3.0f, z2, -1.0f);
        sr[7  * 33] = 1.0925484305920792f * x * z;
        sr[8  * 33] = 0.5462742152960396f * (x2 - y2);
        sr[9  * 33] = 0.5900435899266435f * y * fmaf(3.0f, x2, -y2);
        sr[10 * 33] = 2.890611442640554f  * x * y * z;
        sr[11 * 33] = 0.4570457994644658f * y * fmaf(5.0f, z2, -1.0f);
        sr[12 * 33] = 0.3731763325901154f * z * fmaf(5.0f, z2, -3.0f);
        sr[13 * 33] = 0.4570457994644658f * x * fmaf(5.0f, z2, -1.0f);
        sr[14 * 33] = 1.445305721320277f  * z * (x2 - y2);
        sr[15 * 33] = 0.5900435899266435f * x * (x2 - y2);
    }
    __syncwarp();

    // segment detection over sorted bucket ids
    int b_up = __shfl_up_sync(0xffffffffu, b, 1);
    bool head = (lane == 0) || (b != b_up);
    unsigned hm = __ballot_sync(0xffffffffu, head);

    int myk  = lane >> 1;
    int half = lane & 1;
    int l    = (myk >= 9) ? 3 : ((myk >= 4) ? 2 : ((myk >= 1) ? 1 : 0));
    int q    = l * 2 + half;
    const float* shrow  = &s_sh[w][myk * 33];
    const float* radrow = &s_rad[w][q * 132];

    unsigned m = hm;
    while (m) {
        int s = __ffs(m) - 1;
        m &= m - 1;
        int e2 = m ? (__ffs(m) - 1) : 32;
        int bs = s_bkt[w][s];
        if (bs >= 0) {
            float ax = 0.f, ay = 0.f, az = 0.f, aw = 0.f;
            for (int i = s; i < e2; i++) {
                float sk = shrow[i];
                float4 r = *reinterpret_cast<const float4*>(&radrow[i * 4]);
                ax = fmaf(sk, r.x, ax);
                ay = fmaf(sk, r.y, ay);
                az = fmaf(sk, r.z, az);
                aw = fmaf(sk, r.w, aw);
            }
            float* p = out + ((bs >> 2) * 512 + myk * 32 + (bs & 3) * 8 + half * 4);
            red_add_v4(p, ax, ay, az, aw);
        }
    }
}

} // namespace

extern "C" void kernel_launch(void* const* d_in, const int* in_sizes, int n_in,
                              void* d_out, int out_size)
{
    const float* vectors = (const float*)d_in[0];
    const float* W       = (const float*)d_in[1];
    const int*   cidx    = (const int*)d_in[2];
    const int*   sidx    = (const int*)d_in[3];
    float*       out     = (float*)d_out;

    int n_edges = in_sizes[2];

    static void* cnt_ptr = nullptr;
    if (!cnt_ptr) cudaGetSymbolAddress(&cnt_ptr, g_cnt);

    cudaMemsetAsync(d_out, 0, (size_t)out_size * sizeof(float), 0);
    cudaMemsetAsync(cnt_ptr, 0, NB * sizeof(int), 0);

    k_hist<<<(n_edges / 2 + 255) / 256, 256>>>(cidx, sidx, n_edges);
    k_scanA<<<128, 256>>>();
    k_scanC<<<128, 256>>>();
    k_scatter<<<(n_edges / 2 + 255) / 256, 256>>>(vectors, cidx, sidx, n_edges);
    k_accum<<<(n_edges + 255) / 256, 256>>>(W, out, n_edges);
}